// round 1
// baseline (speedup 1.0000x reference)
#include <cuda_runtime.h>
#include <cstddef>

#define N_NODES 65536
#define KTAPS   27
#define COUT    128
#define BN_EPS  1e-3f

#define NT 64          // nodes per block tile
#define CC 32          // input-channel chunk
#define GSTRIDE 68     // Gs row stride (16B-aligned, limits conflicts)

// ---------------- scratch (static device memory; no allocs allowed) ----------------
__device__ float g_xT [(size_t)N_NODES * 64];            // x transposed [N,64]
__device__ float g_wTa[(size_t)KTAPS * 64  * COUT];      // w_a  -> [k][c][o]
__device__ float g_wTb[(size_t)KTAPS * 128 * COUT];      // w_b  -> [k][c][o]
__device__ float g_wTs[(size_t)64 * COUT];               // w_skip -> [c][o]
__device__ float g_ya [(size_t)N_NODES * COUT];          // conv_a out, node-major [N,128]
__device__ float g_yb [(size_t)COUT * N_NODES];          // conv_b out, ch-major [128,N]
__device__ float g_sk [(size_t)COUT * N_NODES];          // skip out,  ch-major [128,N]
__device__ float g_scale_a[COUT];
__device__ float g_bias_a [COUT];
__device__ float g_coef[4 * COUT];                       // [sb, bb, ss, bs]

// ---------------- x transpose: x[c][n] -> xT[n][c] ----------------
__global__ void transpose_x_kernel(const float* __restrict__ x) {
    __shared__ float tile[32][33];
    int nb = blockIdx.x * 32, cb = blockIdx.y * 32;
    int tx = threadIdx.x, ty = threadIdx.y;
#pragma unroll
    for (int i = 0; i < 4; i++)
        tile[ty + i * 8][tx] = x[(size_t)(cb + ty + i * 8) * N_NODES + nb + tx];
    __syncthreads();
#pragma unroll
    for (int i = 0; i < 4; i++)
        g_xT[(size_t)(nb + ty + i * 8) * 64 + cb + tx] = tile[tx][ty + i * 8];
}

// ---------------- weight transpose: w[o][c][k] -> wT[k][c][o] ----------------
__global__ void wtrans_kernel(const float* __restrict__ w, float* __restrict__ wT,
                              int C, int K) {
    int idx = blockIdx.x * 256 + threadIdx.x;
    int total = COUT * C * K;
    if (idx >= total) return;
    int o = idx / (C * K);
    int r = idx - o * (C * K);
    int c = r / K;
    int k = r - c * K;
    wT[((size_t)k * C + c) * COUT + o] = w[idx];
}

// ---------------- gathered conv GEMM ----------------
// out[o,n] = sum_{c,k} f(src[neigh[n,k], c]) * wT[k][c][o]
// f = identity, or BN+relu (fused for conv_b input).
template<int CIN, int KT, bool GATHER, bool FUSE>
__global__ __launch_bounds__(256)
void conv_kernel(const float* __restrict__ src,
                 const float* __restrict__ wT,
                 const int*   __restrict__ neigh,
                 const float* __restrict__ isc,
                 const float* __restrict__ ibi,
                 float* __restrict__ out,
                 int out_node_major) {
    __shared__ __align__(16) float Ws[CC * COUT];       // [c][o]
    __shared__ __align__(16) float Gs[CC * GSTRIDE];    // [c][n]
    __shared__ int Js[NT];

    const int n_base = blockIdx.x * NT;
    const int t  = threadIdx.x;
    const int tn = t & 7;        // 0..7
    const int to = t >> 3;       // 0..31
    const int o0 = to * 4;
    const int n0 = tn * 8;

    float acc[4][8];
#pragma unroll
    for (int a = 0; a < 4; a++)
#pragma unroll
        for (int b = 0; b < 8; b++) acc[a][b] = 0.f;

    for (int k = 0; k < KT; ++k) {
        if (GATHER) {
            if (t < NT) Js[t] = neigh[(size_t)(n_base + t) * KTAPS + k];
        }
        __syncthreads();
#pragma unroll 1
        for (int cc = 0; cc < CIN; cc += CC) {
            // --- stage weights: CC*COUT floats = 1024 float4, 4 per thread ---
            const float4* wp = (const float4*)(wT + ((size_t)k * CIN + cc) * COUT);
#pragma unroll
            for (int i = 0; i < 4; i++)
                ((float4*)Ws)[t + i * 256] = wp[t + i * 256];
            // --- stage gathered inputs: CC*NT floats = 512 float4, 2 per thread ---
#pragma unroll
            for (int i = 0; i < 2; i++) {
                int q  = t + i * 256;       // 0..511
                int n  = q >> 3;            // node within tile
                int c0 = (q & 7) * 4;       // channel quad within chunk
                int j  = GATHER ? Js[n] : (n_base + n);
                float4 g = *(const float4*)(src + (size_t)j * CIN + cc + c0);
                if (FUSE) {
                    float4 sc = *(const float4*)(isc + cc + c0);
                    float4 bi = *(const float4*)(ibi + cc + c0);
                    g.x = fmaxf(fmaf(g.x, sc.x, bi.x), 0.f);
                    g.y = fmaxf(fmaf(g.y, sc.y, bi.y), 0.f);
                    g.z = fmaxf(fmaf(g.z, sc.z, bi.z), 0.f);
                    g.w = fmaxf(fmaf(g.w, sc.w, bi.w), 0.f);
                }
                Gs[(c0 + 0) * GSTRIDE + n] = g.x;
                Gs[(c0 + 1) * GSTRIDE + n] = g.y;
                Gs[(c0 + 2) * GSTRIDE + n] = g.z;
                Gs[(c0 + 3) * GSTRIDE + n] = g.w;
            }
            __syncthreads();
            // --- compute: 32 FMAs per ci per thread ---
#pragma unroll
            for (int ci = 0; ci < CC; ++ci) {
                float4 w  = *(const float4*)&Ws[ci * COUT + o0];
                float4 ga = *(const float4*)&Gs[ci * GSTRIDE + n0];
                float4 gb = *(const float4*)&Gs[ci * GSTRIDE + n0 + 4];
                float wv[4] = {w.x, w.y, w.z, w.w};
                float gv[8] = {ga.x, ga.y, ga.z, ga.w, gb.x, gb.y, gb.z, gb.w};
#pragma unroll
                for (int a = 0; a < 4; a++)
#pragma unroll
                    for (int b = 0; b < 8; b++)
                        acc[a][b] = fmaf(wv[a], gv[b], acc[a][b]);
            }
            __syncthreads();
        }
    }

    if (out_node_major) {
#pragma unroll
        for (int b = 0; b < 8; b++) {
            float4 v = make_float4(acc[0][b], acc[1][b], acc[2][b], acc[3][b]);
            *(float4*)&out[(size_t)(n_base + n0 + b) * COUT + o0] = v;
        }
    } else {
#pragma unroll
        for (int a = 0; a < 4; a++) {
            float4 v0 = make_float4(acc[a][0], acc[a][1], acc[a][2], acc[a][3]);
            float4 v1 = make_float4(acc[a][4], acc[a][5], acc[a][6], acc[a][7]);
            *(float4*)&out[(size_t)(o0 + a) * N_NODES + n_base + n0]     = v0;
            *(float4*)&out[(size_t)(o0 + a) * N_NODES + n_base + n0 + 4] = v1;
        }
    }
}

// ---------------- BN stats over node-major y [N,128] -> scale/bias ----------------
__global__ void stats_nm_kernel(const float* __restrict__ y,
                                const float* __restrict__ gamma,
                                const float* __restrict__ beta,
                                float* __restrict__ scale,
                                float* __restrict__ bias) {
    int c = blockIdx.x;
    float s = 0.f, q = 0.f;
    for (int n = threadIdx.x; n < N_NODES; n += 256) {
        float v = y[(size_t)n * COUT + c];
        s += v; q += v * v;
    }
    __shared__ float rs[256], rq[256];
    rs[threadIdx.x] = s; rq[threadIdx.x] = q;
    __syncthreads();
    for (int st = 128; st > 0; st >>= 1) {
        if (threadIdx.x < st) {
            rs[threadIdx.x] += rs[threadIdx.x + st];
            rq[threadIdx.x] += rq[threadIdx.x + st];
        }
        __syncthreads();
    }
    if (threadIdx.x == 0) {
        float mean = rs[0] / N_NODES;
        float var  = rq[0] / N_NODES - mean * mean;
        float kk   = gamma[c] * rsqrtf(var + BN_EPS);
        scale[c] = kk;
        bias[c]  = beta[c] - kk * mean;
    }
}

// ---------------- BN stats over ch-major y_b and skip, fused finalize ----------------
__global__ void stats_om_kernel(const float* __restrict__ yb,
                                const float* __restrict__ sk,
                                const float* __restrict__ gb,
                                const float* __restrict__ bb,
                                const float* __restrict__ gs,
                                const float* __restrict__ bs,
                                float* __restrict__ coef) {
    int c = blockIdx.x;
    const float4* pb = (const float4*)(yb + (size_t)c * N_NODES);
    const float4* ps = (const float4*)(sk + (size_t)c * N_NODES);
    float s1 = 0.f, q1 = 0.f, s2 = 0.f, q2 = 0.f;
    for (int i = threadIdx.x; i < N_NODES / 4; i += 256) {
        float4 a = pb[i];
        s1 += a.x + a.y + a.z + a.w;
        q1 += a.x * a.x + a.y * a.y + a.z * a.z + a.w * a.w;
        float4 b = ps[i];
        s2 += b.x + b.y + b.z + b.w;
        q2 += b.x * b.x + b.y * b.y + b.z * b.z + b.w * b.w;
    }
    __shared__ float r1[256], r2[256], r3[256], r4[256];
    r1[threadIdx.x] = s1; r2[threadIdx.x] = q1;
    r3[threadIdx.x] = s2; r4[threadIdx.x] = q2;
    __syncthreads();
    for (int st = 128; st > 0; st >>= 1) {
        if (threadIdx.x < st) {
            r1[threadIdx.x] += r1[threadIdx.x + st];
            r2[threadIdx.x] += r2[threadIdx.x + st];
            r3[threadIdx.x] += r3[threadIdx.x + st];
            r4[threadIdx.x] += r4[threadIdx.x + st];
        }
        __syncthreads();
    }
    if (threadIdx.x == 0) {
        float m1 = r1[0] / N_NODES, v1 = r2[0] / N_NODES - m1 * m1;
        float k1 = gb[c] * rsqrtf(v1 + BN_EPS);
        coef[c]            = k1;
        coef[COUT + c]     = bb[c] - k1 * m1;
        float m2 = r3[0] / N_NODES, v2 = r4[0] / N_NODES - m2 * m2;
        float k2 = gs[c] * rsqrtf(v2 + BN_EPS);
        coef[2 * COUT + c] = k2;
        coef[3 * COUT + c] = bs[c] - k2 * m2;
    }
}

// ---------------- final: out = relu(BN_b(y_b) + BN_s(skip)) ----------------
__global__ void final_ew_kernel(const float* __restrict__ yb,
                                const float* __restrict__ sk,
                                const float* __restrict__ coef,
                                float* __restrict__ out) {
    int i = blockIdx.x * 256 + threadIdx.x;   // quad index; 128*16384 total
    int o = i >> 14;                          // 16384 quads per channel
    float sb = coef[o],            bb = coef[COUT + o];
    float ss = coef[2 * COUT + o], bs = coef[3 * COUT + o];
    float4 a = ((const float4*)yb)[i];
    float4 b = ((const float4*)sk)[i];
    float4 r;
    r.x = fmaxf(fmaf(sb, a.x, bb) + fmaf(ss, b.x, bs), 0.f);
    r.y = fmaxf(fmaf(sb, a.y, bb) + fmaf(ss, b.y, bs), 0.f);
    r.z = fmaxf(fmaf(sb, a.z, bb) + fmaf(ss, b.z, bs), 0.f);
    r.w = fmaxf(fmaf(sb, a.w, bb) + fmaf(ss, b.w, bs), 0.f);
    ((float4*)out)[i] = r;
}

// ---------------- host ----------------
extern "C" void kernel_launch(void* const* d_in, const int* in_sizes, int n_in,
                              void* d_out, int out_size) {
    const float* data    = (const float*)d_in[0];
    const int*   neigh   = (const int*)  d_in[1];
    const float* w_a     = (const float*)d_in[2];
    const float* w_b     = (const float*)d_in[3];
    const float* w_skip  = (const float*)d_in[4];
    const float* gamma_a = (const float*)d_in[5];
    const float* beta_a  = (const float*)d_in[6];
    const float* gamma_b = (const float*)d_in[7];
    const float* beta_b  = (const float*)d_in[8];
    const float* gamma_s = (const float*)d_in[9];
    const float* beta_s  = (const float*)d_in[10];
    float* out = (float*)d_out;

    float *xT, *wTa, *wTb, *wTs, *ya, *yb, *sk, *sca, *bia, *coef;
    cudaGetSymbolAddress((void**)&xT,   g_xT);
    cudaGetSymbolAddress((void**)&wTa,  g_wTa);
    cudaGetSymbolAddress((void**)&wTb,  g_wTb);
    cudaGetSymbolAddress((void**)&wTs,  g_wTs);
    cudaGetSymbolAddress((void**)&ya,   g_ya);
    cudaGetSymbolAddress((void**)&yb,   g_yb);
    cudaGetSymbolAddress((void**)&sk,   g_sk);
    cudaGetSymbolAddress((void**)&sca,  g_scale_a);
    cudaGetSymbolAddress((void**)&bia,  g_bias_a);
    cudaGetSymbolAddress((void**)&coef, g_coef);

    // 1) layout transforms
    transpose_x_kernel<<<dim3(N_NODES / 32, 2), dim3(32, 8)>>>(data);
    wtrans_kernel<<<(COUT * 64  * KTAPS + 255) / 256, 256>>>(w_a,    wTa, 64,  KTAPS);
    wtrans_kernel<<<(COUT * 128 * KTAPS + 255) / 256, 256>>>(w_b,    wTb, 128, KTAPS);
    wtrans_kernel<<<(COUT * 64        + 255) / 256, 256>>>(w_skip, wTs, 64,  1);

    const int grid = N_NODES / NT;   // 1024

    // 2) conv_a (gathered GEMM), node-major output for next gather
    conv_kernel<64, KTAPS, true, false><<<grid, 256>>>(
        xT, wTa, neigh, nullptr, nullptr, ya, 1);

    // 3) BN_a stats -> scale_a/bias_a
    stats_nm_kernel<<<COUT, 256>>>(ya, gamma_a, beta_a, sca, bia);

    // 4) conv_b: gather + fused BN_a+relu on input, ch-major output
    conv_kernel<128, KTAPS, true, true><<<grid, 256>>>(
        ya, wTb, neigh, sca, bia, yb, 0);

    // 5) skip = w_skip @ x (same GEMM, K=1, identity gather), ch-major output
    conv_kernel<64, 1, false, false><<<grid, 256>>>(
        xT, wTs, nullptr, nullptr, nullptr, sk, 0);

    // 6) BN_b + BN_s stats + coefficient finalize
    stats_om_kernel<<<COUT, 256>>>(yb, sk, gamma_b, beta_b, gamma_s, beta_s, coef);

    // 7) out = relu(BN_b(y_b) + BN_s(skip))
    final_ew_kernel<<<(COUT * N_NODES / 4) / 256, 256>>>(yb, sk, coef, out);
}

// round 3
// speedup vs baseline: 2.6411x; 2.6411x over previous
#include <cuda_runtime.h>
#include <cuda_bf16.h>
#include <cstddef>
#include <cstdint>

#define N_NODES 65536
#define KTAPS   27
#define COUT    128
#define BN_EPS  1e-3f

// ==================== warp MMA helpers (base sm_103 target — no tcgen05) ====================
__device__ __forceinline__ uint32_t smem_to_u32(const void* p) {
    uint32_t a;
    asm("{ .reg .u64 t; cvta.to.shared.u64 t, %1; cvt.u32.u64 %0, t; }" : "=r"(a) : "l"(p));
    return a;
}
__device__ __forceinline__ void ldsm_x4(uint32_t& r0, uint32_t& r1, uint32_t& r2, uint32_t& r3,
                                        uint32_t addr) {
    asm volatile("ldmatrix.sync.aligned.m8n8.x4.shared.b16 {%0,%1,%2,%3}, [%4];"
                 : "=r"(r0), "=r"(r1), "=r"(r2), "=r"(r3) : "r"(addr));
}
__device__ __forceinline__ void mma_bf16(float* c, const uint32_t* a, const uint32_t* b) {
    asm volatile(
        "mma.sync.aligned.m16n8k16.row.col.f32.bf16.bf16.f32 "
        "{%0,%1,%2,%3}, {%4,%5,%6,%7}, {%8,%9}, {%0,%1,%2,%3};"
        : "+f"(c[0]), "+f"(c[1]), "+f"(c[2]), "+f"(c[3])
        : "r"(a[0]), "r"(a[1]), "r"(a[2]), "r"(a[3]), "r"(b[0]), "r"(b[1]));
}

// ==================== scratch (static device memory; no allocs) ====================
__device__ __nv_bfloat16 g_xhi[(size_t)N_NODES * 64];
__device__ __nv_bfloat16 g_xlo[(size_t)N_NODES * 64];
__device__ __nv_bfloat16 g_wa_hi[(size_t)KTAPS * 128 * 64];
__device__ __nv_bfloat16 g_wa_lo[(size_t)KTAPS * 128 * 64];
__device__ __nv_bfloat16 g_wb_hi[(size_t)KTAPS * 2 * 128 * 64];
__device__ __nv_bfloat16 g_wb_lo[(size_t)KTAPS * 2 * 128 * 64];
__device__ __nv_bfloat16 g_ws_hi[(size_t)128 * 64];
__device__ __nv_bfloat16 g_ws_lo[(size_t)128 * 64];
__device__ float g_ya[(size_t)N_NODES * COUT];     // conv_a out, node-major
__device__ float g_yb[(size_t)COUT * N_NODES];     // conv_b out, ch-major
__device__ float g_sk[(size_t)COUT * N_NODES];     // skip out,  ch-major
__device__ float g_scale_a[COUT];
__device__ float g_bias_a[COUT];
__device__ float g_coef[4 * COUT];

// ==================== x transpose + bf16 hi/lo split ====================
__global__ void xsplit_kernel(const float* __restrict__ x,
                              __nv_bfloat16* __restrict__ xhi,
                              __nv_bfloat16* __restrict__ xlo) {
    __shared__ float tile[32][33];
    int nb = blockIdx.x * 32, cb = blockIdx.y * 32;
    int tx = threadIdx.x, ty = threadIdx.y;
#pragma unroll
    for (int i = 0; i < 4; i++)
        tile[ty + i * 8][tx] = x[(size_t)(cb + ty + i * 8) * N_NODES + nb + tx];
    __syncthreads();
#pragma unroll
    for (int i = 0; i < 4; i++) {
        float v = tile[tx][ty + i * 8];
        __nv_bfloat16 h = __float2bfloat16(v);
        size_t idx = (size_t)(nb + ty + i * 8) * 64 + cb + tx;
        xhi[idx] = h;
        xlo[idx] = __float2bfloat16(v - __bfloat162float(h));
    }
}

// ==================== weight transpose + split: w[o][c][k] -> [k][ch][o][cl] ====================
__global__ void wsplit_kernel(const float* __restrict__ w,
                              __nv_bfloat16* __restrict__ whi,
                              __nv_bfloat16* __restrict__ wlo,
                              int C, int K) {
    int i = blockIdx.x * 256 + threadIdx.x;
    int total = 128 * C * K;
    if (i >= total) return;
    int CH = C / 64;
    int cl = i & 63;
    int o  = (i >> 6) & 127;
    int kc = i >> 13;
    int ch = kc % CH;
    int k  = kc / CH;
    int c  = ch * 64 + cl;
    float v = w[((size_t)o * C + c) * K + k];
    __nv_bfloat16 h = __float2bfloat16(v);
    whi[i] = h;
    wlo[i] = __float2bfloat16(v - __bfloat162float(h));
}

// ==================== tensor-core gathered conv (warp mma.sync path) ====================
// D[node 0..127, out 0..127] = sum_{k,c} act[node,k,c] * w[out,k,c]
// 3-pass bf16 split (hi*hi + lo*hi + hi*lo), fp32 register accumulators.
template<int CIN, int KT, bool GATHER, bool FUSE, bool PRESPLIT, bool CHMAJOR>
__global__ __launch_bounds__(256, 1)
void tconv_kernel(const __nv_bfloat16* __restrict__ src_hi,
                  const __nv_bfloat16* __restrict__ src_lo,
                  const float* __restrict__ src32,
                  const __nv_bfloat16* __restrict__ w_hi,
                  const __nv_bfloat16* __restrict__ w_lo,
                  const int* __restrict__ neigh,
                  const float* __restrict__ isc,
                  const float* __restrict__ ibi,
                  float* __restrict__ out) {
    constexpr int CH = CIN / 64;
    constexpr int STEPS = KT * CH;
    constexpr int RS = 144;                 // smem row stride bytes (64ch*2B + 16 pad)
    constexpr uint32_t AH = 0, AL = 18432, WH = 36864, WL = 55296;
    extern __shared__ __align__(16) char smem[];
    const uint32_t sb = smem_to_u32(smem);

    const int t = threadIdx.x;
    const int lane = t & 31, wid = t >> 5;
    const int n_base = blockIdx.x * 128;
    const int warp_m = (wid & 1) * 64;      // node offset within tile
    const int warp_n = (wid >> 1) * 32;     // out-ch offset
    // ldmatrix lane address bases (K-major operands, non-trans)
    const uint32_t aoff = sb + (uint32_t)(warp_m + (lane & 15)) * RS + ((lane & 16) ? 16u : 0u);
    const uint32_t boff = sb + (uint32_t)(warp_n + (lane & 7) + ((lane & 16) ? 8 : 0)) * RS
                             + ((lane & 8) ? 16u : 0u);

    float acc[4][4][4];
#pragma unroll
    for (int mi = 0; mi < 4; mi++)
#pragma unroll
        for (int ni = 0; ni < 4; ni++)
#pragma unroll
            for (int e = 0; e < 4; e++) acc[mi][ni][e] = 0.f;

    const int row = t >> 1, part = t & 1;
    const int wrow = wid * 16 + (lane & 15);         // weight smem row this thread fills
    const int wsegbase = (lane >> 4) << 2;           // 0 or 4

    float4 pa[8];
    float4 pwh[4], pwl[4];
    int pj = 0;

    auto prefetch = [&](int s) {
        const int k = s / CH, ch = s % CH;
        pj = GATHER ? neigh[(size_t)(n_base + row) * KTAPS + k] : (n_base + row);
        if (PRESPLIT) {
            const float4* hr = (const float4*)(src_hi + (size_t)pj * CIN) + part * 4;
            const float4* lr = (const float4*)(src_lo + (size_t)pj * CIN) + part * 4;
#pragma unroll
            for (int i = 0; i < 4; i++) { pa[i] = hr[i]; pa[4 + i] = lr[i]; }
        } else {
            const float4* r = (const float4*)(src32 + (size_t)pj * CIN + ch * 64) + part * 8;
#pragma unroll
            for (int i = 0; i < 8; i++) pa[i] = r[i];
        }
        const float4* wh4 = (const float4*)(w_hi + (size_t)(k * CH + ch) * 8192);
        const float4* wl4 = (const float4*)(w_lo + (size_t)(k * CH + ch) * 8192);
#pragma unroll
        for (int i = 0; i < 4; i++) {
            int idx = wrow * 8 + wsegbase + i;
            pwh[i] = wh4[idx];
            pwl[i] = wl4[idx];
        }
    };

    auto store_stage = [&](int s) {
        const int ch = s % CH;
        (void)ch;
        if (PRESPLIT) {
            uint32_t base = (uint32_t)row * RS + part * 64;
#pragma unroll
            for (int i = 0; i < 4; i++) {
                *(float4*)(smem + AH + base + i * 16) = pa[i];
                *(float4*)(smem + AL + base + i * 16) = pa[4 + i];
            }
        } else {
#pragma unroll
            for (int i = 0; i < 8; i++) {
                float4 g = pa[i];
                if (FUSE) {
                    int cabs = ch * 64 + part * 32 + i * 4;
                    float4 sc = *(const float4*)(isc + cabs);
                    float4 bi = *(const float4*)(ibi + cabs);
                    g.x = fmaxf(fmaf(g.x, sc.x, bi.x), 0.f);
                    g.y = fmaxf(fmaf(g.y, sc.y, bi.y), 0.f);
                    g.z = fmaxf(fmaf(g.z, sc.z, bi.z), 0.f);
                    g.w = fmaxf(fmaf(g.w, sc.w, bi.w), 0.f);
                }
                __nv_bfloat16 hx = __float2bfloat16(g.x);
                __nv_bfloat16 hy = __float2bfloat16(g.y);
                __nv_bfloat16 hz = __float2bfloat16(g.z);
                __nv_bfloat16 hw = __float2bfloat16(g.w);
                float lx = g.x - __bfloat162float(hx);
                float ly = g.y - __bfloat162float(hy);
                float lz = g.z - __bfloat162float(hz);
                float lw = g.w - __bfloat162float(hw);
                uint32_t off = (uint32_t)row * RS + (part * 32 + i * 4) * 2;
                *(__nv_bfloat162*)(smem + AH + off)     = __nv_bfloat162(hx, hy);
                *(__nv_bfloat162*)(smem + AH + off + 4) = __nv_bfloat162(hz, hw);
                *(__nv_bfloat162*)(smem + AL + off)     = __floats2bfloat162_rn(lx, ly);
                *(__nv_bfloat162*)(smem + AL + off + 4) = __floats2bfloat162_rn(lz, lw);
            }
        }
#pragma unroll
        for (int i = 0; i < 4; i++) {
            uint32_t woff = (uint32_t)wrow * RS + (wsegbase + i) * 16;
            *(float4*)(smem + WH + woff) = pwh[i];
            *(float4*)(smem + WL + woff) = pwl[i];
        }
    };

    prefetch(0);

    for (int s = 0; s < STEPS; ++s) {
        __syncthreads();                 // previous compute done, smem reusable
        store_stage(s);
        __syncthreads();                 // stage visible
        if (s + 1 < STEPS) prefetch(s + 1);   // LDGs in flight during compute

#pragma unroll
        for (int k16 = 0; k16 < 4; ++k16) {
            const uint32_t kb = (uint32_t)k16 * 32;
            uint32_t ah[4][4], bh[4][2];
#pragma unroll
            for (int mi = 0; mi < 4; mi++)
                ldsm_x4(ah[mi][0], ah[mi][1], ah[mi][2], ah[mi][3],
                        aoff + AH + mi * (16 * RS) + kb);
#pragma unroll
            for (int nt = 0; nt < 2; nt++) {
                uint32_t r0, r1, r2, r3;
                ldsm_x4(r0, r1, r2, r3, boff + WH + nt * (16 * RS) + kb);
                bh[2 * nt][0] = r0; bh[2 * nt][1] = r1;
                bh[2 * nt + 1][0] = r2; bh[2 * nt + 1][1] = r3;
            }
#pragma unroll
            for (int mi = 0; mi < 4; mi++)
#pragma unroll
                for (int ni = 0; ni < 4; ni++)
                    mma_bf16(acc[mi][ni], ah[mi], bh[ni]);
            // pass 2: lo(act) * hi(w)
            {
                uint32_t al[4][4];
#pragma unroll
                for (int mi = 0; mi < 4; mi++)
                    ldsm_x4(al[mi][0], al[mi][1], al[mi][2], al[mi][3],
                            aoff + AL + mi * (16 * RS) + kb);
#pragma unroll
                for (int mi = 0; mi < 4; mi++)
#pragma unroll
                    for (int ni = 0; ni < 4; ni++)
                        mma_bf16(acc[mi][ni], al[mi], bh[ni]);
            }
            // pass 3: hi(act) * lo(w)
            {
                uint32_t bl[4][2];
#pragma unroll
                for (int nt = 0; nt < 2; nt++) {
                    uint32_t r0, r1, r2, r3;
                    ldsm_x4(r0, r1, r2, r3, boff + WL + nt * (16 * RS) + kb);
                    bl[2 * nt][0] = r0; bl[2 * nt][1] = r1;
                    bl[2 * nt + 1][0] = r2; bl[2 * nt + 1][1] = r3;
                }
#pragma unroll
                for (int mi = 0; mi < 4; mi++)
#pragma unroll
                    for (int ni = 0; ni < 4; ni++)
                        mma_bf16(acc[mi][ni], ah[mi], bl[ni]);
            }
        }
    }

    // ---- epilogue ----
#pragma unroll
    for (int mi = 0; mi < 4; mi++)
#pragma unroll
        for (int ni = 0; ni < 4; ni++) {
            int r = n_base + warp_m + mi * 16 + (lane >> 2);
            int c = warp_n + ni * 8 + (lane & 3) * 2;
            if (CHMAJOR) {
                out[(size_t)c * N_NODES + r]           = acc[mi][ni][0];
                out[(size_t)(c + 1) * N_NODES + r]     = acc[mi][ni][1];
                out[(size_t)c * N_NODES + r + 8]       = acc[mi][ni][2];
                out[(size_t)(c + 1) * N_NODES + r + 8] = acc[mi][ni][3];
            } else {
                *(float2*)&out[(size_t)r * COUT + c] =
                    make_float2(acc[mi][ni][0], acc[mi][ni][1]);
                *(float2*)&out[(size_t)(r + 8) * COUT + c] =
                    make_float2(acc[mi][ni][2], acc[mi][ni][3]);
            }
        }
}

// ==================== BN stats, node-major y [N,128] ====================
__global__ void stats_nm_kernel(const float* __restrict__ y,
                                const float* __restrict__ gamma,
                                const float* __restrict__ beta,
                                float* __restrict__ scale,
                                float* __restrict__ bias) {
    int c = blockIdx.x;
    float s = 0.f, q = 0.f;
    for (int n = threadIdx.x; n < N_NODES; n += 256) {
        float v = y[(size_t)n * COUT + c];
        s += v; q += v * v;
    }
    __shared__ float rs[256], rq[256];
    rs[threadIdx.x] = s; rq[threadIdx.x] = q;
    __syncthreads();
    for (int st = 128; st > 0; st >>= 1) {
        if (threadIdx.x < st) {
            rs[threadIdx.x] += rs[threadIdx.x + st];
            rq[threadIdx.x] += rq[threadIdx.x + st];
        }
        __syncthreads();
    }
    if (threadIdx.x == 0) {
        float mean = rs[0] / N_NODES;
        float var  = rq[0] / N_NODES - mean * mean;
        float kk   = gamma[c] * rsqrtf(var + BN_EPS);
        scale[c] = kk;
        bias[c]  = beta[c] - kk * mean;
    }
}

// ==================== BN stats over ch-major yb & sk ====================
__global__ void stats_om_kernel(const float* __restrict__ yb,
                                const float* __restrict__ sk,
                                const float* __restrict__ gb,
                                const float* __restrict__ bb,
                                const float* __restrict__ gs,
                                const float* __restrict__ bs,
                                float* __restrict__ coef) {
    int c = blockIdx.x;
    const float4* pb = (const float4*)(yb + (size_t)c * N_NODES);
    const float4* ps = (const float4*)(sk + (size_t)c * N_NODES);
    float s1 = 0.f, q1 = 0.f, s2 = 0.f, q2 = 0.f;
    for (int i = threadIdx.x; i < N_NODES / 4; i += 256) {
        float4 a = pb[i];
        s1 += a.x + a.y + a.z + a.w;
        q1 += a.x * a.x + a.y * a.y + a.z * a.z + a.w * a.w;
        float4 b = ps[i];
        s2 += b.x + b.y + b.z + b.w;
        q2 += b.x * b.x + b.y * b.y + b.z * b.z + b.w * b.w;
    }
    __shared__ float r1[256], r2[256], r3[256], r4[256];
    r1[threadIdx.x] = s1; r2[threadIdx.x] = q1;
    r3[threadIdx.x] = s2; r4[threadIdx.x] = q2;
    __syncthreads();
    for (int st = 128; st > 0; st >>= 1) {
        if (threadIdx.x < st) {
            r1[threadIdx.x] += r1[threadIdx.x + st];
            r2[threadIdx.x] += r2[threadIdx.x + st];
            r3[threadIdx.x] += r3[threadIdx.x + st];
            r4[threadIdx.x] += r4[threadIdx.x + st];
        }
        __syncthreads();
    }
    if (threadIdx.x == 0) {
        float m1 = r1[0] / N_NODES, v1 = r2[0] / N_NODES - m1 * m1;
        float k1 = gb[c] * rsqrtf(v1 + BN_EPS);
        coef[c]            = k1;
        coef[COUT + c]     = bb[c] - k1 * m1;
        float m2 = r3[0] / N_NODES, v2 = r4[0] / N_NODES - m2 * m2;
        float k2 = gs[c] * rsqrtf(v2 + BN_EPS);
        coef[2 * COUT + c] = k2;
        coef[3 * COUT + c] = bs[c] - k2 * m2;
    }
}

// ==================== final: out = relu(BN_b(yb) + BN_s(sk)) ====================
__global__ void final_ew_kernel(const float* __restrict__ yb,
                                const float* __restrict__ sk,
                                const float* __restrict__ coef,
                                float* __restrict__ out) {
    int i = blockIdx.x * 256 + threadIdx.x;
    int o = i >> 14;
    float sb = coef[o],            bb = coef[COUT + o];
    float ss = coef[2 * COUT + o], bs = coef[3 * COUT + o];
    float4 a = ((const float4*)yb)[i];
    float4 b = ((const float4*)sk)[i];
    float4 r;
    r.x = fmaxf(fmaf(sb, a.x, bb) + fmaf(ss, b.x, bs), 0.f);
    r.y = fmaxf(fmaf(sb, a.y, bb) + fmaf(ss, b.y, bs), 0.f);
    r.z = fmaxf(fmaf(sb, a.z, bb) + fmaf(ss, b.z, bs), 0.f);
    r.w = fmaxf(fmaf(sb, a.w, bb) + fmaf(ss, b.w, bs), 0.f);
    ((float4*)out)[i] = r;
}

// ==================== host ====================
static constexpr int TCONV_SMEM = 73728;

extern "C" void kernel_launch(void* const* d_in, const int* in_sizes, int n_in,
                              void* d_out, int out_size) {
    const float* data    = (const float*)d_in[0];
    const int*   neigh   = (const int*)  d_in[1];
    const float* w_a     = (const float*)d_in[2];
    const float* w_b     = (const float*)d_in[3];
    const float* w_skip  = (const float*)d_in[4];
    const float* gamma_a = (const float*)d_in[5];
    const float* beta_a  = (const float*)d_in[6];
    const float* gamma_b = (const float*)d_in[7];
    const float* beta_b  = (const float*)d_in[8];
    const float* gamma_s = (const float*)d_in[9];
    const float* beta_s  = (const float*)d_in[10];
    float* out = (float*)d_out;

    __nv_bfloat16 *xhi, *xlo, *wah, *wal, *wbh, *wbl, *wsh, *wsl;
    float *ya, *yb, *sk, *sca, *bia, *coef;
    cudaGetSymbolAddress((void**)&xhi, g_xhi);
    cudaGetSymbolAddress((void**)&xlo, g_xlo);
    cudaGetSymbolAddress((void**)&wah, g_wa_hi);
    cudaGetSymbolAddress((void**)&wal, g_wa_lo);
    cudaGetSymbolAddress((void**)&wbh, g_wb_hi);
    cudaGetSymbolAddress((void**)&wbl, g_wb_lo);
    cudaGetSymbolAddress((void**)&wsh, g_ws_hi);
    cudaGetSymbolAddress((void**)&wsl, g_ws_lo);
    cudaGetSymbolAddress((void**)&ya,  g_ya);
    cudaGetSymbolAddress((void**)&yb,  g_yb);
    cudaGetSymbolAddress((void**)&sk,  g_sk);
    cudaGetSymbolAddress((void**)&sca, g_scale_a);
    cudaGetSymbolAddress((void**)&bia, g_bias_a);
    cudaGetSymbolAddress((void**)&coef, g_coef);

    auto* ka = tconv_kernel<64, KTAPS, true, false, true, false>;
    auto* kb = tconv_kernel<128, KTAPS, true, true, false, true>;
    auto* ks = tconv_kernel<64, 1, false, false, true, true>;
    cudaFuncSetAttribute(ka, cudaFuncAttributeMaxDynamicSharedMemorySize, TCONV_SMEM);
    cudaFuncSetAttribute(kb, cudaFuncAttributeMaxDynamicSharedMemorySize, TCONV_SMEM);
    cudaFuncSetAttribute(ks, cudaFuncAttributeMaxDynamicSharedMemorySize, TCONV_SMEM);

    // 1) layout transforms + precision splits
    xsplit_kernel<<<dim3(N_NODES / 32, 2), dim3(32, 8)>>>(data, xhi, xlo);
    wsplit_kernel<<<(KTAPS * 64 * 128 + 255) / 256, 256>>>(w_a, wah, wal, 64, KTAPS);
    wsplit_kernel<<<(KTAPS * 128 * 128 + 255) / 256, 256>>>(w_b, wbh, wbl, 128, KTAPS);
    wsplit_kernel<<<(64 * 128 + 255) / 256, 256>>>(w_skip, wsh, wsl, 64, 1);

    const int grid = N_NODES / 128;   // 512

    // 2) conv_a (HMMA), node-major out
    ka<<<grid, 256, TCONV_SMEM>>>(xhi, xlo, nullptr, wah, wal, neigh,
                                  nullptr, nullptr, ya);
    // 3) BN_a stats
    stats_nm_kernel<<<COUT, 256>>>(ya, gamma_a, beta_a, sca, bia);
    // 4) conv_b (HMMA, fused BN_a+relu on gathered input), ch-major out
    kb<<<grid, 256, TCONV_SMEM>>>(nullptr, nullptr, ya, wbh, wbl, neigh,
                                  sca, bia, yb);
    // 5) skip (HMMA, no gather), ch-major out
    ks<<<grid, 256, TCONV_SMEM>>>(xhi, xlo, nullptr, wsh, wsl, nullptr,
                                  nullptr, nullptr, sk);
    // 6) BN_b + BN_s stats
    stats_om_kernel<<<COUT, 256>>>(yb, sk, gamma_b, beta_b, gamma_s, beta_s, coef);
    // 7) final elementwise
    final_ew_kernel<<<(COUT * N_NODES / 4) / 256, 256>>>(yb, sk, coef, out);
}

// round 4
// speedup vs baseline: 3.1345x; 1.1868x over previous
#include <cuda_runtime.h>
#include <cuda_bf16.h>
#include <cstddef>
#include <cstdint>

#define N_NODES 65536
#define KTAPS   27
#define COUT    128
#define BN_EPS  1e-3f

// ==================== helpers ====================
__device__ __forceinline__ uint32_t smem_to_u32(const void* p) {
    uint32_t a;
    asm("{ .reg .u64 t; cvta.to.shared.u64 t, %1; cvt.u32.u64 %0, t; }" : "=r"(a) : "l"(p));
    return a;
}
__device__ __forceinline__ void ldsm_x4(uint32_t& r0, uint32_t& r1, uint32_t& r2, uint32_t& r3,
                                        uint32_t addr) {
    asm volatile("ldmatrix.sync.aligned.m8n8.x4.shared.b16 {%0,%1,%2,%3}, [%4];"
                 : "=r"(r0), "=r"(r1), "=r"(r2), "=r"(r3) : "r"(addr));
}
__device__ __forceinline__ void mma_bf16(float* c, const uint32_t* a, const uint32_t* b) {
    asm volatile(
        "mma.sync.aligned.m16n8k16.row.col.f32.bf16.bf16.f32 "
        "{%0,%1,%2,%3}, {%4,%5,%6,%7}, {%8,%9}, {%0,%1,%2,%3};"
        : "+f"(c[0]), "+f"(c[1]), "+f"(c[2]), "+f"(c[3])
        : "r"(a[0]), "r"(a[1]), "r"(a[2]), "r"(a[3]), "r"(b[0]), "r"(b[1]));
}
__device__ __forceinline__ void cp16(uint32_t s, const void* g) {
    asm volatile("{ .reg .u64 gg; cvta.to.global.u64 gg, %1;"
                 "  cp.async.cg.shared.global [%0], [gg], 16; }"
                 :: "r"(s), "l"(g) : "memory");
}
#define CP_COMMIT() asm volatile("cp.async.commit_group;" ::: "memory")
#define CP_WAIT1()  asm volatile("cp.async.wait_group 1;" ::: "memory")
#define CP_WAIT0()  asm volatile("cp.async.wait_group 0;" ::: "memory")

// ==================== scratch (static device memory; no allocs) ====================
__device__ __nv_bfloat16 g_xhi[(size_t)N_NODES * 64];
__device__ __nv_bfloat16 g_xlo[(size_t)N_NODES * 64];
__device__ __nv_bfloat16 g_wa_hi[(size_t)KTAPS * 128 * 64];
__device__ __nv_bfloat16 g_wa_lo[(size_t)KTAPS * 128 * 64];
__device__ __nv_bfloat16 g_wb_hi[(size_t)KTAPS * 2 * 128 * 64];
__device__ __nv_bfloat16 g_wb_lo[(size_t)KTAPS * 2 * 128 * 64];
__device__ __nv_bfloat16 g_ws_hi[(size_t)128 * 64];
__device__ __nv_bfloat16 g_ws_lo[(size_t)128 * 64];
__device__ float g_ya[(size_t)N_NODES * COUT];            // conv_a out fp32, node-major
__device__ __nv_bfloat16 g_yahi[(size_t)N_NODES * COUT];  // relu(BN_a(ya)) split
__device__ __nv_bfloat16 g_yalo[(size_t)N_NODES * COUT];
__device__ float g_yb[(size_t)COUT * N_NODES];            // conv_b out, ch-major
__device__ float g_sk[(size_t)COUT * N_NODES];            // skip out,  ch-major
__device__ float g_stat[2 * COUT];                        // [sum, sumsq]
__device__ float g_scale_a[COUT];
__device__ float g_bias_a[COUT];
__device__ float g_coef[4 * COUT];

// ==================== tiny: zero stat accumulators ====================
__global__ void zero_stat_kernel(float* acc) { acc[threadIdx.x] = 0.f; }

// ==================== x transpose + bf16 hi/lo split ====================
__global__ void xsplit_kernel(const float* __restrict__ x,
                              __nv_bfloat16* __restrict__ xhi,
                              __nv_bfloat16* __restrict__ xlo) {
    __shared__ float tile[32][33];
    int nb = blockIdx.x * 32, cb = blockIdx.y * 32;
    int tx = threadIdx.x, ty = threadIdx.y;
#pragma unroll
    for (int i = 0; i < 4; i++)
        tile[ty + i * 8][tx] = x[(size_t)(cb + ty + i * 8) * N_NODES + nb + tx];
    __syncthreads();
#pragma unroll
    for (int i = 0; i < 4; i++) {
        float v = tile[tx][ty + i * 8];
        __nv_bfloat16 h = __float2bfloat16(v);
        size_t idx = (size_t)(nb + ty + i * 8) * 64 + cb + tx;
        xhi[idx] = h;
        xlo[idx] = __float2bfloat16(v - __bfloat162float(h));
    }
}

// ==================== weight transpose + split: w[o][c][k] -> [k][ch][o][cl] ====================
__global__ void wsplit_kernel(const float* __restrict__ w,
                              __nv_bfloat16* __restrict__ whi,
                              __nv_bfloat16* __restrict__ wlo,
                              int C, int K) {
    int i = blockIdx.x * 256 + threadIdx.x;
    int total = 128 * C * K;
    if (i >= total) return;
    int CH = C / 64;
    int cl = i & 63;
    int o  = (i >> 6) & 127;
    int kc = i >> 13;
    int ch = kc % CH;
    int k  = kc / CH;
    int c  = ch * 64 + cl;
    float v = w[((size_t)o * C + c) * K + k];
    __nv_bfloat16 h = __float2bfloat16(v);
    whi[i] = h;
    wlo[i] = __float2bfloat16(v - __bfloat162float(h));
}

// ==================== gathered conv GEMM on HMMA, cp.async 3-stage ring ====================
// D[node 0..127, out 0..127] = sum_{k,c} act[node,k,c] * w[out,k,c]
// 3-pass bf16 split (hi*hi + lo*hi + hi*lo), fp32 register accumulators.
template<int CIN, int KT, bool GATHER, bool CHMAJOR>
__global__ __launch_bounds__(256, 1)
void tconv_kernel(const __nv_bfloat16* __restrict__ src_hi,
                  const __nv_bfloat16* __restrict__ src_lo,
                  const __nv_bfloat16* __restrict__ w_hi,
                  const __nv_bfloat16* __restrict__ w_lo,
                  const int* __restrict__ neigh,
                  float* __restrict__ out) {
    constexpr int CH = CIN / 64;
    constexpr int STEPS = KT * CH;
    constexpr int RS = 144;
    constexpr uint32_t AH = 0, AL = 18432, WH = 36864, WL = 55296, BUF = 73728;
    extern __shared__ __align__(16) char smem[];
    const uint32_t sb = smem_to_u32(smem);

    const int t = threadIdx.x;
    const int lane = t & 31, wid = t >> 5;
    const int n_base = blockIdx.x * 128;
    const int warp_m = (wid & 1) * 64;
    const int warp_n = (wid >> 1) * 32;
    const uint32_t aoff_lane = (uint32_t)(warp_m + (lane & 15)) * RS + ((lane & 16) ? 16u : 0u);
    const uint32_t boff_lane = (uint32_t)(warp_n + (lane & 7) + ((lane & 16) ? 8 : 0)) * RS
                               + ((lane & 8) ? 16u : 0u);

    const int row  = t >> 1, part = t & 1;
    const int wrow = wid * 16 + (lane & 15);
    const int wseg = (lane >> 4) << 2;

    float acc[4][4][4];
#pragma unroll
    for (int mi = 0; mi < 4; mi++)
#pragma unroll
        for (int ni = 0; ni < 4; ni++)
#pragma unroll
            for (int e = 0; e < 4; e++) acc[mi][ni][e] = 0.f;

    auto j_of = [&](int s) -> int {
        return GATHER ? neigh[(size_t)(n_base + row) * KT + (s / CH)] : (n_base + row);
    };

    auto issue = [&](int s, int j) {
        const uint32_t stg = sb + (uint32_t)(s % 3) * BUF;
        const int k = s / CH, ch = s % CH;
        const __nv_bfloat16* ah = src_hi + (size_t)j * CIN + ch * 64 + part * 32;
        const __nv_bfloat16* al = src_lo + (size_t)j * CIN + ch * 64 + part * 32;
        const uint32_t ab = stg + AH + (uint32_t)row * RS + part * 64;
        const uint32_t lb = stg + AL + (uint32_t)row * RS + part * 64;
#pragma unroll
        for (int i = 0; i < 4; i++) {
            cp16(ab + i * 16, ah + i * 8);
            cp16(lb + i * 16, al + i * 8);
        }
        const __nv_bfloat16* wh = w_hi + ((size_t)(k * CH + ch) << 13) + wrow * 64 + wseg * 8;
        const __nv_bfloat16* wl = w_lo + ((size_t)(k * CH + ch) << 13) + wrow * 64 + wseg * 8;
        const uint32_t wbh = stg + WH + (uint32_t)wrow * RS + wseg * 16;
        const uint32_t wbl = stg + WL + (uint32_t)wrow * RS + wseg * 16;
#pragma unroll
        for (int i = 0; i < 4; i++) {
            cp16(wbh + i * 16, wh + i * 8);
            cp16(wbl + i * 16, wl + i * 8);
        }
        CP_COMMIT();
    };

    int jn = j_of(0);
    issue(0, jn);
    if (STEPS > 1) jn = j_of(1);

    for (int s = 0; s < STEPS; ++s) {
        if (s + 1 < STEPS) {
            issue(s + 1, jn);
            if (s + 2 < STEPS) jn = j_of(s + 2);
            CP_WAIT1();
        } else {
            CP_WAIT0();
        }
        __syncthreads();

        const uint32_t sbuf = sb + (uint32_t)(s % 3) * BUF;
        const uint32_t a_h = sbuf + AH + aoff_lane;
        const uint32_t a_l = sbuf + AL + aoff_lane;
        const uint32_t b_h = sbuf + WH + boff_lane;
        const uint32_t b_l = sbuf + WL + boff_lane;

#pragma unroll
        for (int k16 = 0; k16 < 4; ++k16) {
            const uint32_t kb = (uint32_t)k16 * 32;
            uint32_t ah[4][4], bh[4][2];
#pragma unroll
            for (int mi = 0; mi < 4; mi++)
                ldsm_x4(ah[mi][0], ah[mi][1], ah[mi][2], ah[mi][3],
                        a_h + mi * (16 * RS) + kb);
#pragma unroll
            for (int nt = 0; nt < 2; nt++) {
                uint32_t r0, r1, r2, r3;
                ldsm_x4(r0, r1, r2, r3, b_h + nt * (16 * RS) + kb);
                bh[2 * nt][0] = r0; bh[2 * nt][1] = r1;
                bh[2 * nt + 1][0] = r2; bh[2 * nt + 1][1] = r3;
            }
#pragma unroll
            for (int mi = 0; mi < 4; mi++)
#pragma unroll
                for (int ni = 0; ni < 4; ni++)
                    mma_bf16(acc[mi][ni], ah[mi], bh[ni]);
            {   // pass 2: lo(act) * hi(w)
                uint32_t al4[4][4];
#pragma unroll
                for (int mi = 0; mi < 4; mi++)
                    ldsm_x4(al4[mi][0], al4[mi][1], al4[mi][2], al4[mi][3],
                            a_l + mi * (16 * RS) + kb);
#pragma unroll
                for (int mi = 0; mi < 4; mi++)
#pragma unroll
                    for (int ni = 0; ni < 4; ni++)
                        mma_bf16(acc[mi][ni], al4[mi], bh[ni]);
            }
            {   // pass 3: hi(act) * lo(w)
                uint32_t bl[4][2];
#pragma unroll
                for (int nt = 0; nt < 2; nt++) {
                    uint32_t r0, r1, r2, r3;
                    ldsm_x4(r0, r1, r2, r3, b_l + nt * (16 * RS) + kb);
                    bl[2 * nt][0] = r0; bl[2 * nt][1] = r1;
                    bl[2 * nt + 1][0] = r2; bl[2 * nt + 1][1] = r3;
                }
#pragma unroll
                for (int mi = 0; mi < 4; mi++)
#pragma unroll
                    for (int ni = 0; ni < 4; ni++)
                        mma_bf16(acc[mi][ni], ah[mi], bl[ni]);
            }
        }
    }

    // ---- epilogue ----
#pragma unroll
    for (int mi = 0; mi < 4; mi++)
#pragma unroll
        for (int ni = 0; ni < 4; ni++) {
            int r = n_base + warp_m + mi * 16 + (lane >> 2);
            int c = warp_n + ni * 8 + (lane & 3) * 2;
            if (CHMAJOR) {
                out[(size_t)c * N_NODES + r]           = acc[mi][ni][0];
                out[(size_t)(c + 1) * N_NODES + r]     = acc[mi][ni][1];
                out[(size_t)c * N_NODES + r + 8]       = acc[mi][ni][2];
                out[(size_t)(c + 1) * N_NODES + r + 8] = acc[mi][ni][3];
            } else {
                *(float2*)&out[(size_t)r * COUT + c] =
                    make_float2(acc[mi][ni][0], acc[mi][ni][1]);
                *(float2*)&out[(size_t)(r + 8) * COUT + c] =
                    make_float2(acc[mi][ni][2], acc[mi][ni][3]);
            }
        }
}

// ==================== BN_a stats: coalesced partial sums + atomics ====================
__global__ void stats_nm_kernel(const float* __restrict__ y, float* __restrict__ acc) {
    const int t = threadIdx.x;
    const int c = t & 127, half = t >> 7;
    const int nb = blockIdx.x * 1024;
    float s = 0.f, q = 0.f;
    for (int n = nb + half; n < nb + 1024; n += 2) {
        float v = y[(size_t)n * COUT + c];
        s += v; q += v * v;
    }
    __shared__ float rs[256], rq[256];
    rs[t] = s; rq[t] = q;
    __syncthreads();
    if (half == 0) {
        atomicAdd(&acc[c],        rs[t] + rs[t + 128]);
        atomicAdd(&acc[COUT + c], rq[t] + rq[t + 128]);
    }
}

// ==================== BN_a finalize ====================
__global__ void stats_fin_kernel(const float* __restrict__ acc,
                                 const float* __restrict__ gamma,
                                 const float* __restrict__ beta,
                                 float* __restrict__ scale,
                                 float* __restrict__ bias) {
    int c = threadIdx.x;
    float mean = acc[c] / N_NODES;
    float var  = acc[COUT + c] / N_NODES - mean * mean;
    float kk   = gamma[c] * rsqrtf(var + BN_EPS);
    scale[c] = kk;
    bias[c]  = beta[c] - kk * mean;
}

// ==================== yasplit: relu(BN_a(ya)) -> bf16 hi/lo ====================
__global__ void yasplit_kernel(const float* __restrict__ ya,
                               const float* __restrict__ scale,
                               const float* __restrict__ bias,
                               __nv_bfloat16* __restrict__ yhi,
                               __nv_bfloat16* __restrict__ ylo) {
    int i = blockIdx.x * 256 + threadIdx.x;      // quad index
    int c0 = (i & 31) * 4;
    float4 v  = ((const float4*)ya)[i];
    float4 sc = *(const float4*)(scale + c0);
    float4 bi = *(const float4*)(bias + c0);
    float a0 = fmaxf(fmaf(v.x, sc.x, bi.x), 0.f);
    float a1 = fmaxf(fmaf(v.y, sc.y, bi.y), 0.f);
    float a2 = fmaxf(fmaf(v.z, sc.z, bi.z), 0.f);
    float a3 = fmaxf(fmaf(v.w, sc.w, bi.w), 0.f);
    __nv_bfloat16 h0 = __float2bfloat16(a0), h1 = __float2bfloat16(a1);
    __nv_bfloat16 h2 = __float2bfloat16(a2), h3 = __float2bfloat16(a3);
    ((__nv_bfloat162*)yhi)[i * 2]     = __nv_bfloat162(h0, h1);
    ((__nv_bfloat162*)yhi)[i * 2 + 1] = __nv_bfloat162(h2, h3);
    ((__nv_bfloat162*)ylo)[i * 2]     = __floats2bfloat162_rn(a0 - __bfloat162float(h0),
                                                              a1 - __bfloat162float(h1));
    ((__nv_bfloat162*)ylo)[i * 2 + 1] = __floats2bfloat162_rn(a2 - __bfloat162float(h2),
                                                              a3 - __bfloat162float(h3));
}

// ==================== BN stats over ch-major yb & sk ====================
__global__ void stats_om_kernel(const float* __restrict__ yb,
                                const float* __restrict__ sk,
                                const float* __restrict__ gb,
                                const float* __restrict__ bb,
                                const float* __restrict__ gs,
                                const float* __restrict__ bs,
                                float* __restrict__ coef) {
    int c = blockIdx.x;
    const float4* pb = (const float4*)(yb + (size_t)c * N_NODES);
    const float4* ps = (const float4*)(sk + (size_t)c * N_NODES);
    float s1 = 0.f, q1 = 0.f, s2 = 0.f, q2 = 0.f;
    for (int i = threadIdx.x; i < N_NODES / 4; i += 256) {
        float4 a = pb[i];
        s1 += a.x + a.y + a.z + a.w;
        q1 += a.x * a.x + a.y * a.y + a.z * a.z + a.w * a.w;
        float4 b = ps[i];
        s2 += b.x + b.y + b.z + b.w;
        q2 += b.x * b.x + b.y * b.y + b.z * b.z + b.w * b.w;
    }
    __shared__ float r1[256], r2[256], r3[256], r4[256];
    r1[threadIdx.x] = s1; r2[threadIdx.x] = q1;
    r3[threadIdx.x] = s2; r4[threadIdx.x] = q2;
    __syncthreads();
    for (int st = 128; st > 0; st >>= 1) {
        if (threadIdx.x < st) {
            r1[threadIdx.x] += r1[threadIdx.x + st];
            r2[threadIdx.x] += r2[threadIdx.x + st];
            r3[threadIdx.x] += r3[threadIdx.x + st];
            r4[threadIdx.x] += r4[threadIdx.x + st];
        }
        __syncthreads();
    }
    if (threadIdx.x == 0) {
        float m1 = r1[0] / N_NODES, v1 = r2[0] / N_NODES - m1 * m1;
        float k1 = gb[c] * rsqrtf(v1 + BN_EPS);
        coef[c]            = k1;
        coef[COUT + c]     = bb[c] - k1 * m1;
        float m2 = r3[0] / N_NODES, v2 = r4[0] / N_NODES - m2 * m2;
        float k2 = gs[c] * rsqrtf(v2 + BN_EPS);
        coef[2 * COUT + c] = k2;
        coef[3 * COUT + c] = bs[c] - k2 * m2;
    }
}

// ==================== final: out = relu(BN_b(yb) + BN_s(sk)) ====================
__global__ void final_ew_kernel(const float* __restrict__ yb,
                                const float* __restrict__ sk,
                                const float* __restrict__ coef,
                                float* __restrict__ out) {
    int i = blockIdx.x * 256 + threadIdx.x;
    int o = i >> 14;
    float sb = coef[o],            bb = coef[COUT + o];
    float ss = coef[2 * COUT + o], bs = coef[3 * COUT + o];
    float4 a = ((const float4*)yb)[i];
    float4 b = ((const float4*)sk)[i];
    float4 r;
    r.x = fmaxf(fmaf(sb, a.x, bb) + fmaf(ss, b.x, bs), 0.f);
    r.y = fmaxf(fmaf(sb, a.y, bb) + fmaf(ss, b.y, bs), 0.f);
    r.z = fmaxf(fmaf(sb, a.z, bb) + fmaf(ss, b.z, bs), 0.f);
    r.w = fmaxf(fmaf(sb, a.w, bb) + fmaf(ss, b.w, bs), 0.f);
    ((float4*)out)[i] = r;
}

// ==================== host ====================
static constexpr int TCONV_SMEM = 3 * 73728;   // 221184 B

extern "C" void kernel_launch(void* const* d_in, const int* in_sizes, int n_in,
                              void* d_out, int out_size) {
    const float* data    = (const float*)d_in[0];
    const int*   neigh   = (const int*)  d_in[1];
    const float* w_a     = (const float*)d_in[2];
    const float* w_b     = (const float*)d_in[3];
    const float* w_skip  = (const float*)d_in[4];
    const float* gamma_a = (const float*)d_in[5];
    const float* beta_a  = (const float*)d_in[6];
    const float* gamma_b = (const float*)d_in[7];
    const float* beta_b  = (const float*)d_in[8];
    const float* gamma_s = (const float*)d_in[9];
    const float* beta_s  = (const float*)d_in[10];
    float* out = (float*)d_out;

    __nv_bfloat16 *xhi, *xlo, *wah, *wal, *wbh, *wbl, *wsh, *wsl, *yahi, *yalo;
    float *ya, *yb, *sk, *stat, *sca, *bia, *coef;
    cudaGetSymbolAddress((void**)&xhi,  g_xhi);
    cudaGetSymbolAddress((void**)&xlo,  g_xlo);
    cudaGetSymbolAddress((void**)&wah,  g_wa_hi);
    cudaGetSymbolAddress((void**)&wal,  g_wa_lo);
    cudaGetSymbolAddress((void**)&wbh,  g_wb_hi);
    cudaGetSymbolAddress((void**)&wbl,  g_wb_lo);
    cudaGetSymbolAddress((void**)&wsh,  g_ws_hi);
    cudaGetSymbolAddress((void**)&wsl,  g_ws_lo);
    cudaGetSymbolAddress((void**)&ya,   g_ya);
    cudaGetSymbolAddress((void**)&yahi, g_yahi);
    cudaGetSymbolAddress((void**)&yalo, g_yalo);
    cudaGetSymbolAddress((void**)&yb,   g_yb);
    cudaGetSymbolAddress((void**)&sk,   g_sk);
    cudaGetSymbolAddress((void**)&stat, g_stat);
    cudaGetSymbolAddress((void**)&sca,  g_scale_a);
    cudaGetSymbolAddress((void**)&bia,  g_bias_a);
    cudaGetSymbolAddress((void**)&coef, g_coef);

    auto* ka = tconv_kernel<64, KTAPS, true, false>;
    auto* kb = tconv_kernel<128, KTAPS, true, true>;
    auto* ks = tconv_kernel<64, 1, false, true>;
    cudaFuncSetAttribute(ka, cudaFuncAttributeMaxDynamicSharedMemorySize, TCONV_SMEM);
    cudaFuncSetAttribute(kb, cudaFuncAttributeMaxDynamicSharedMemorySize, TCONV_SMEM);
    cudaFuncSetAttribute(ks, cudaFuncAttributeMaxDynamicSharedMemorySize, TCONV_SMEM);

    // layout transforms + precision splits
    zero_stat_kernel<<<1, 256>>>(stat);
    xsplit_kernel<<<dim3(N_NODES / 32, 2), dim3(32, 8)>>>(data, xhi, xlo);
    wsplit_kernel<<<(KTAPS * 64 * 128 + 255) / 256, 256>>>(w_a, wah, wal, 64, KTAPS);
    wsplit_kernel<<<(KTAPS * 128 * 128 + 255) / 256, 256>>>(w_b, wbh, wbl, 128, KTAPS);
    wsplit_kernel<<<(64 * 128 + 255) / 256, 256>>>(w_skip, wsh, wsl, 64, 1);

    const int grid = N_NODES / 128;   // 512

    // conv_a (HMMA), node-major fp32 out
    ka<<<grid, 256, TCONV_SMEM>>>(xhi, xlo, wah, wal, neigh, ya);
    // BN_a stats + finalize + split c1 to bf16 hi/lo
    stats_nm_kernel<<<64, 256>>>(ya, stat);
    stats_fin_kernel<<<1, 128>>>(stat, gamma_a, beta_a, sca, bia);
    yasplit_kernel<<<(N_NODES * COUT / 4) / 256, 256>>>(ya, sca, bia, yahi, yalo);
    // conv_b (HMMA, presplit gathered input), ch-major out
    kb<<<grid, 256, TCONV_SMEM>>>(yahi, yalo, wbh, wbl, neigh, yb);
    // skip (HMMA, no gather), ch-major out
    ks<<<grid, 256, TCONV_SMEM>>>(xhi, xlo, wsh, wsl, nullptr, sk);
    // BN_b + BN_s stats
    stats_om_kernel<<<COUT, 256>>>(yb, sk, gamma_b, beta_b, gamma_s, beta_s, coef);
    // final elementwise
    final_ew_kernel<<<(COUT * N_NODES / 4) / 256, 256>>>(yb, sk, coef, out);
}